// round 13
// baseline (speedup 1.0000x reference)
#include <cuda_runtime.h>
#include <cuda_fp16.h>
#include <float.h>
#include <cstdint>

#define NB   16
#define TT   4096
#define DD   64
#define KK   1024
#define SS   8
#define NV   (NB*TT)
#define TM   64
#define ZQ_ELEMS (NB*DD*TT)

// ---- device scratch ----
__device__ float        g_res[NV*DD];     // initial residual
__device__ float        g_q[NV*DD];
// fragment-packed codebook (hi, uint4-kpair): [stage][blk(128)][kpair(2)][lane(32)][8 halves]
__device__ __half       g_cbfrag[SS*128*2*32*8];
__device__ float        g_hn[SS*KK];      // NEGATED halfnorms: -0.5*||c||^2
__device__ float        g_loss[SS];
__device__ unsigned int g_cnt[SS*KK];

// ---- smem layout (bytes) ----
#define RSTR     144            // Ah row stride bytes (72 fp16)
#define RSTRF    68             // Af row stride floats (272B)
#define SM_HN    0              // 32768
#define SM_RED   32768          // 8 stages * 8 warps * 4 = 256
#define SM_TOP4  33024          // 64*4*4 = 1024
#define SM_M4V   34048          // 64*16*4 = 4096
#define SM_AF    38144          // 64*272 = 17408
#define SM_AH    55552          // 64*144 = 9216
#define SM_TOTAL 64768

// ---- PTX helpers ----
__device__ __forceinline__ void cpa16(uint32_t daddr, const void* src) {
    asm volatile("cp.async.cg.shared.global [%0], [%1], 16;" :: "r"(daddr), "l"(src) : "memory");
}
__device__ __forceinline__ void cpa_commit() { asm volatile("cp.async.commit_group;" ::: "memory"); }
__device__ __forceinline__ void cpa_wait0()  { asm volatile("cp.async.wait_group 0;" ::: "memory"); }

__device__ __forceinline__ void ldsm_x4(uint32_t* r, uint32_t a) {
    asm volatile("ldmatrix.sync.aligned.m8n8.x4.shared.b16 {%0,%1,%2,%3}, [%4];"
        : "=r"(r[0]), "=r"(r[1]), "=r"(r[2]), "=r"(r[3]) : "r"(a));
}
__device__ __forceinline__ void mma16816(float* c, const uint32_t* a, uint32_t b0, uint32_t b1) {
    asm volatile("mma.sync.aligned.m16n8k16.row.col.f32.f16.f16.f32 "
        "{%0,%1,%2,%3}, {%4,%5,%6,%7}, {%8,%9}, {%0,%1,%2,%3};"
        : "+f"(c[0]), "+f"(c[1]), "+f"(c[2]), "+f"(c[3])
        : "r"(a[0]), "r"(a[1]), "r"(a[2]), "r"(a[3]), "r"(b0), "r"(b1));
}

// pack 9-bit pair-id into low mantissa bits (perturbation <= 2^-14 relative)
__device__ __forceinline__ float packf(float v, int pid) {
    return __uint_as_float((__float_as_uint(v) & 0xFFFFFE00u) | (unsigned)pid);
}

// ---- transpose z [B,D,T] -> g_res [(b,t),d] ----
__global__ void transpose_in(const float* __restrict__ z) {
    __shared__ float tile[32][33];
    const int b  = blockIdx.z;
    const int t0 = blockIdx.x * 32;
    const int d0 = blockIdx.y * 32;
    #pragma unroll
    for (int j = 0; j < 32; j += 8)
        tile[threadIdx.y + j][threadIdx.x] = z[(b*DD + d0 + threadIdx.y + j)*TT + t0 + threadIdx.x];
    __syncthreads();
    #pragma unroll
    for (int j = 0; j < 32; j += 8) {
        int t = t0 + threadIdx.y + j;
        int d = d0 + threadIdx.x;
        g_res[(b*TT + t)*DD + d] = tile[threadIdx.x][threadIdx.y + j];
    }
}

__global__ void transpose_out(float* __restrict__ out) {
    __shared__ float tile[32][33];
    const int b  = blockIdx.z;
    const int t0 = blockIdx.x * 32;
    const int d0 = blockIdx.y * 32;
    #pragma unroll
    for (int j = 0; j < 32; j += 8)
        tile[threadIdx.y + j][threadIdx.x] = g_q[((size_t)b*TT + t0 + threadIdx.y + j)*DD + d0 + threadIdx.x];
    __syncthreads();
    #pragma unroll
    for (int j = 0; j < 32; j += 8)
        out[((size_t)b*DD + d0 + threadIdx.y + j)*TT + t0 + threadIdx.x] = tile[threadIdx.x][threadIdx.y + j];
}

// ---- codebook -> fragment-packed uint4 layout + NEGATED halfnorms ----
__global__ void cb_split(const float* __restrict__ cbs) {
    int g = blockIdx.x * 128 + threadIdx.x;   // 0..8191 = s*1024 + j
    int s    = g >> 10;
    int j    = g & 1023;
    int blk  = j >> 3;
    int n_ib = j & 7;
    const float* src = cbs + (size_t)g * DD;
    float s2 = 0.0f;
    #pragma unroll
    for (int k = 0; k < DD; k++) {
        float v = src[k];
        s2 += v*v;
        __half h = __float2half_rn(v);
        int kstep = k >> 4, kk = k & 15;
        int kpair = kstep >> 1, kodd = kstep & 1;
        int reg  = kk >> 3;
        int lane = n_ib*4 + ((kk & 7) >> 1);
        int elem = kk & 1;
        size_t idx = ((((size_t)s*128 + blk)*2 + kpair)*32 + lane)*8 + kodd*4 + reg*2 + elem;
        g_cbfrag[idx] = h;
    }
    g_hn[g] = -0.5f * s2;
}

__global__ void zero_acc() {
    int i = blockIdx.x * 256 + threadIdx.x;
    if (i < SS*KK) g_cnt[i] = 0u;
    if (i < SS)    g_loss[i] = 0.0f;
}

// ---- fused all-stages kernel ----
extern __shared__ char smem_raw[];

#define LOADU(buf, blkbase, p) { \
    _Pragma("unroll") \
    for (int i_ = 0; i_ < 4; i_++) buf[i_] = __ldg(bf4 + (((blkbase) + i_)*2 + (p))*32); }

#define MMAU(base, buf, p) { \
    _Pragma("unroll") \
    for (int i_ = 0; i_ < 4; i_++) { \
        mma16816(acc[(base)+i_], ahf[2*(p)],   buf[i_].x, buf[i_].y); \
        mma16816(acc[(base)+i_], ahf[2*(p)+1], buf[i_].z, buf[i_].w); } }

__global__ __launch_bounds__(256, 2)
void rvq_all(const float* __restrict__ cbs) {
    const int tid  = threadIdx.x;
    const int w    = tid >> 5;
    const int lane = tid & 31;
    const int lq   = lane & 3;
    const int wrow = w >> 1;          // 0..3: rows wrow*16..+15
    const int wcol = w & 1;           // 0..1: blocks wcol*64..+63
    const int row0 = blockIdx.x * TM;
    uint32_t sb;
    asm("{ .reg .u64 t; cvta.to.shared.u64 t, %1; cvt.u32.u64 %0, t; }" : "=r"(sb) : "l"(smem_raw));

    float* hn_all = (float*)(smem_raw + SM_HN);
    float* red    = (float*)(smem_raw + SM_RED);
    float* top4   = (float*)(smem_raw + SM_TOP4);
    float* m4v    = (float*)(smem_raw + SM_M4V);
    float* Af     = (float*)(smem_raw + SM_AF);

    // ---- prologue: fp32 residual tile + ALL stages' (negated) halfnorms ----
    {
        const char* af = (const char*)(g_res + (size_t)row0*DD);
        #pragma unroll
        for (int g = 0; g < 4; g++) {
            int idx = g*256 + tid;              // 1024 granules
            int r = idx >> 4, c = idx & 15;
            cpa16(sb + SM_AF + r*(RSTRF*4) + c*16, af + r*256 + c*16);
        }
        #pragma unroll
        for (int g = 0; g < 8; g++) {
            int idx = g*256 + tid;              // 2048 granules
            cpa16(sb + SM_HN + idx*16, (const char*)g_hn + idx*16);
        }
        cpa_commit();
        cpa_wait0();
    }
    __syncthreads();

    const uint32_t a_addr = sb + SM_AH + (wrow*16 + (lane & 15))*RSTR + (lane >> 4)*16;
    const int r0   = wrow*16 + (lane >> 2);   // thread's first row
    const int slot = wcol*4 + lq;

    for (int stage = 0; stage < SS; stage++) {
        const float* hns = hn_all + stage*KK;
        const float* cb  = cbs + (size_t)stage*KK*DD;

        // build Ah (fp16) from Af — reads only this thread's own quarter-row
        {
            int r  = tid >> 2;
            int k0 = lq * 16;
            const float* src = Af + r*RSTRF + k0;
            __half2* dst = (__half2*)(smem_raw + SM_AH + r*RSTR + k0*2);
            #pragma unroll
            for (int j = 0; j < 8; j++)
                dst[j] = __floats2half2_rn(src[j*2], src[j*2+1]);
        }
        __syncthreads();   // (1) Ah visible to all

        uint32_t ahf[4][4];
        #pragma unroll
        for (int s = 0; s < 4; s++) ldsm_x4(ahf[s], a_addr + s*32);

        const uint4* bf4 = ((const uint4*)g_cbfrag) + (size_t)stage*8192 + lane;

        float v00 = -FLT_MAX, v10 = -FLT_MAX;   // row0 packed top-2
        float v01 = -FLT_MAX, v11 = -FLT_MAX;   // row1 packed top-2

        uint4 bufA[4], bufB[4];
        LOADU(bufA, wcol*64, 0);
        for (int cg = 0; cg < 8; cg++) {
            const int blk0  = wcol*64 + cg*8;
            const int cbase = blk0*8 + lq*2;

            // init accumulators with NEGATED halfnorms (float2 loads)
            float acc[8][4];
            #pragma unroll
            for (int nb = 0; nb < 8; nb++) {
                float2 h2 = *(const float2*)(hns + cbase + nb*8);
                acc[nb][0] = h2.x; acc[nb][1] = h2.y;
                acc[nb][2] = h2.x; acc[nb][3] = h2.y;
            }

            LOADU(bufB, blk0 + 4, 0);
            MMAU(0, bufA, 0);
            LOADU(bufA, blk0, 1);
            MMAU(4, bufB, 0);
            LOADU(bufB, blk0 + 4, 1);
            MMAU(0, bufA, 1);
            if (cg < 7) LOADU(bufA, blk0 + 8, 0);
            MMAU(4, bufB, 1);

            // branchless selection: pair cols, pack pair-id, stream top-2
            const int pidb = blk0*4 + lq;
            #pragma unroll
            for (int nb = 0; nb < 8; nb++) {
                float p0 = fmaxf(acc[nb][0], acc[nb][1]);
                float p1 = fmaxf(acc[nb][2], acc[nb][3]);
                p0 = packf(p0, pidb + nb*4);
                p1 = packf(p1, pidb + nb*4);
                float t0 = fminf(v00, p0); v00 = fmaxf(v00, p0); v10 = fmaxf(v10, t0);
                float t1 = fminf(v01, p1); v01 = fmaxf(v01, p1); v11 = fmaxf(v11, t1);
            }
        }

        // ---- write per-thread packed top-2 (16 entries per row) ----
        m4v[r0*16 + slot*2 + 0]     = v00;
        m4v[r0*16 + slot*2 + 1]     = v10;
        m4v[(r0+8)*16 + slot*2 + 0] = v01;
        m4v[(r0+8)*16 + slot*2 + 1] = v11;
        __syncthreads();   // (2)

        // ---- merge: one thread per row, branchless streaming top-4 of 16 ----
        if (tid < TM) {
            float m0 = -FLT_MAX, m1 = -FLT_MAX, m2 = -FLT_MAX, m3 = -FLT_MAX;
            #pragma unroll
            for (int e = 0; e < 16; e++) {
                float x = m4v[tid*16 + e];
                float t0 = fminf(m0, x); m0 = fmaxf(m0, x);
                float t1 = fminf(m1, t0); m1 = fmaxf(m1, t0);
                float t2 = fminf(m2, t1); m2 = fmaxf(m2, t1);
                m3 = fmaxf(m3, t2);
            }
            top4[tid*4 + 0] = m0;
            top4[tid*4 + 1] = m1;
            top4[tid*4 + 2] = m2;
            top4[tid*4 + 3] = m3;
        }
        __syncthreads();   // (3)

        // ---- exact fp32 rescore: 4 threads per row, 2 codes (one pair) each ----
        int idx;
        {
            const int row = tid >> 2;
            const int c   = lq;
            uint32_t pid = __float_as_uint(top4[row*4 + c]) & 0x1FFu;
            int c0 = (int)pid * 2;
            const float4* cp0 = (const float4*)(cb + (size_t)c0*DD);
            const float4* cp1 = (const float4*)(cb + (size_t)(c0+1)*DD);
            const float*  af  = Af + row*RSTRF;
            float s0 = 0.f, s1 = 0.f;
            #pragma unroll
            for (int u = 0; u < 16; u++) {
                float4 q0 = __ldg(cp0 + u);
                float4 q1 = __ldg(cp1 + u);
                float a0 = af[u*4], a1 = af[u*4+1], a2 = af[u*4+2], a3 = af[u*4+3];
                s0 += q0.x*a0 + q0.y*a1 + q0.z*a2 + q0.w*a3;
                s1 += q1.x*a0 + q1.y*a1 + q1.z*a2 + q1.w*a3;
            }
            float sc0 = s0 + hns[c0];
            float sc1 = s1 + hns[c0+1];
            float sc;
            if (sc1 > sc0) { sc = sc1; idx = c0 + 1; }
            else           { sc = sc0; idx = c0; }
            #pragma unroll
            for (int off = 1; off <= 2; off <<= 1) {
                float ov = __shfl_xor_sync(0xffffffffu, sc, off);
                int   oi = __shfl_xor_sync(0xffffffffu, idx, off);
                if (ov > sc || (ov == sc && oi < idx)) { sc = ov; idx = oi; }
            }
            if (c == 0) atomicAdd(&g_cnt[stage*KK + idx], 1u);
        }

        // ---- update residual in smem (own quarter); loss partial ----
        {
            const int row = tid >> 2;
            const float4* qv = (const float4*)(cb + (size_t)idx*DD + lq*16);
            float* af = Af + row*RSTRF + lq*16;
            float lsum = 0.0f;
            #pragma unroll
            for (int u = 0; u < 4; u++) {
                float4 q4 = __ldg(qv + u);
                float e0 = q4.x - af[u*4+0];
                float e1 = q4.y - af[u*4+1];
                float e2 = q4.z - af[u*4+2];
                float e3 = q4.w - af[u*4+3];
                lsum += e0*e0 + e1*e1 + e2*e2 + e3*e3;
                af[u*4+0] = -e0; af[u*4+1] = -e1; af[u*4+2] = -e2; af[u*4+3] = -e3;
            }
            #pragma unroll
            for (int o = 16; o > 0; o >>= 1) lsum += __shfl_down_sync(0xffffffffu, lsum, o);
            if (lane == 0) red[stage*8 + w] = lsum;
        }
        // no block sync needed: next stage's Ah build reads only this thread's own Af quarter
    }

    __syncthreads();
    // deferred loss accumulation: one thread per stage
    if (tid < SS) {
        float tot = 0.0f;
        #pragma unroll
        for (int ww = 0; ww < 8; ww++) tot += red[tid*8 + ww];
        atomicAdd(&g_loss[tid], tot);
    }

    // ---- final: q_total = initial residual - final residual ----
    {
        const int row = tid >> 2;
        const float4* rip = (const float4*)(g_res + (size_t)(row0+row)*DD + lq*16);
        float4*       qp  = (float4*)(g_q   + (size_t)(row0+row)*DD + lq*16);
        const float*  af  = Af + row*RSTRF + lq*16;
        #pragma unroll
        for (int u = 0; u < 4; u++) {
            float4 ri = __ldg(rip + u);
            float4 q;
            q.x = ri.x - af[u*4+0];
            q.y = ri.y - af[u*4+1];
            q.z = ri.z - af[u*4+2];
            q.w = ri.w - af[u*4+3];
            qp[u] = q;
        }
    }
}

// ---- losses + perplexities ----
__global__ void finalize(float* __restrict__ out) {
    const int s = blockIdx.x;
    __shared__ float sh[256];
    float e = 0.0f;
    for (int k = threadIdx.x; k < KK; k += 256) {
        float p = (float)g_cnt[s*KK + k] / (float)NV;
        e += p * logf(p + 1e-10f);
    }
    sh[threadIdx.x] = e;
    __syncthreads();
    for (int o = 128; o > 0; o >>= 1) {
        if (threadIdx.x < o) sh[threadIdx.x] += sh[threadIdx.x + o];
        __syncthreads();
    }
    if (threadIdx.x == 0) {
        out[ZQ_ELEMS + s]      = g_loss[s] / (float)(NV*DD);
        out[ZQ_ELEMS + SS + s] = expf(-sh[0]);
    }
}

extern "C" void kernel_launch(void* const* d_in, const int* in_sizes, int n_in,
                              void* d_out, int out_size) {
    const float* z   = (const float*)d_in[0];
    const float* cbs = (const float*)d_in[1];
    float* out = (float*)d_out;

    static int inited = 0;
    if (!inited) {
        cudaFuncSetAttribute(rvq_all, cudaFuncAttributeMaxDynamicSharedMemorySize, SM_TOTAL);
        inited = 1;
    }

    dim3 tb(32, 8);
    transpose_in<<<dim3(TT/32, DD/32, NB), tb>>>(z);
    zero_acc<<<32, 256>>>();
    cb_split<<<(SS*KK)/128, 128>>>(cbs);
    rvq_all<<<NV/TM, 256, SM_TOTAL>>>(cbs);
    finalize<<<SS, 256>>>(out);
    transpose_out<<<dim3(TT/32, DD/32, NB), tb>>>(out);
}

// round 14
// speedup vs baseline: 1.9772x; 1.9772x over previous
#include <cuda_runtime.h>
#include <cuda_fp16.h>
#include <float.h>
#include <cstdint>

#define NB   16
#define TT   4096
#define DD   64
#define KK   1024
#define SS   8
#define NV   (NB*TT)
#define TM   64
#define ZQ_ELEMS (NB*DD*TT)

// ---- device scratch ----
__device__ float        g_res[NV*DD];     // initial residual
__device__ float        g_q[NV*DD];
// fragment-packed codebook (hi, uint4-kpair): [stage][blk(128)][kpair(2)][lane(32)][8 halves]
__device__ __half       g_cbfrag[SS*128*2*32*8];
__device__ float        g_hn[SS*KK];      // NEGATED halfnorms: -0.5*||c||^2
__device__ float        g_loss[SS];
__device__ unsigned int g_cnt[SS*KK];

// ---- smem layout (bytes) ----
#define RSTR     144            // Ah row stride bytes (72 fp16)
#define RSTRF    68             // Af row stride floats (272B)
#define SM_HN    0              // 32768
#define SM_RED   32768          // 8 stages * 8 warps * 4 = 256
#define SM_TOP4  33024          // 64*4*4 = 1024
#define SM_M4V   34048          // 64*16*4 = 4096
#define SM_AF    38144          // 64*272 = 17408
#define SM_AH    55552          // 64*144 = 9216
#define SM_TOTAL 64768

// ---- PTX helpers ----
__device__ __forceinline__ void cpa16(uint32_t daddr, const void* src) {
    asm volatile("cp.async.cg.shared.global [%0], [%1], 16;" :: "r"(daddr), "l"(src) : "memory");
}
__device__ __forceinline__ void cpa_commit() { asm volatile("cp.async.commit_group;" ::: "memory"); }
__device__ __forceinline__ void cpa_wait0()  { asm volatile("cp.async.wait_group 0;" ::: "memory"); }

__device__ __forceinline__ void ldsm_x4(uint32_t* r, uint32_t a) {
    asm volatile("ldmatrix.sync.aligned.m8n8.x4.shared.b16 {%0,%1,%2,%3}, [%4];"
        : "=r"(r[0]), "=r"(r[1]), "=r"(r[2]), "=r"(r[3]) : "r"(a));
}
__device__ __forceinline__ void mma16816(float* c, const uint32_t* a, uint32_t b0, uint32_t b1) {
    asm volatile("mma.sync.aligned.m16n8k16.row.col.f32.f16.f16.f32 "
        "{%0,%1,%2,%3}, {%4,%5,%6,%7}, {%8,%9}, {%0,%1,%2,%3};"
        : "+f"(c[0]), "+f"(c[1]), "+f"(c[2]), "+f"(c[3])
        : "r"(a[0]), "r"(a[1]), "r"(a[2]), "r"(a[3]), "r"(b0), "r"(b1));
}

// pack 9-bit pair-id into low mantissa bits (perturbation <= 2^-14 relative)
__device__ __forceinline__ float packf(float v, int pid) {
    return __uint_as_float((__float_as_uint(v) & 0xFFFFFE00u) | (unsigned)pid);
}

// ---- transpose z [B,D,T] -> g_res [(b,t),d] ----
__global__ void transpose_in(const float* __restrict__ z) {
    __shared__ float tile[32][33];
    const int b  = blockIdx.z;
    const int t0 = blockIdx.x * 32;
    const int d0 = blockIdx.y * 32;
    #pragma unroll
    for (int j = 0; j < 32; j += 8)
        tile[threadIdx.y + j][threadIdx.x] = z[(b*DD + d0 + threadIdx.y + j)*TT + t0 + threadIdx.x];
    __syncthreads();
    #pragma unroll
    for (int j = 0; j < 32; j += 8) {
        int t = t0 + threadIdx.y + j;
        int d = d0 + threadIdx.x;
        g_res[(b*TT + t)*DD + d] = tile[threadIdx.x][threadIdx.y + j];
    }
}

__global__ void transpose_out(float* __restrict__ out) {
    __shared__ float tile[32][33];
    const int b  = blockIdx.z;
    const int t0 = blockIdx.x * 32;
    const int d0 = blockIdx.y * 32;
    #pragma unroll
    for (int j = 0; j < 32; j += 8)
        tile[threadIdx.y + j][threadIdx.x] = g_q[((size_t)b*TT + t0 + threadIdx.y + j)*DD + d0 + threadIdx.x];
    __syncthreads();
    #pragma unroll
    for (int j = 0; j < 32; j += 8)
        out[((size_t)b*DD + d0 + threadIdx.y + j)*TT + t0 + threadIdx.x] = tile[threadIdx.x][threadIdx.y + j];
}

// ---- codebook -> fragment-packed uint4 layout + NEGATED halfnorms ----
__global__ void cb_split(const float* __restrict__ cbs) {
    int g = blockIdx.x * 128 + threadIdx.x;   // 0..8191 = s*1024 + j
    int s    = g >> 10;
    int j    = g & 1023;
    int blk  = j >> 3;
    int n_ib = j & 7;
    const float* src = cbs + (size_t)g * DD;
    float s2 = 0.0f;
    #pragma unroll
    for (int k = 0; k < DD; k++) {
        float v = src[k];
        s2 += v*v;
        __half h = __float2half_rn(v);
        int kstep = k >> 4, kk = k & 15;
        int kpair = kstep >> 1, kodd = kstep & 1;
        int reg  = kk >> 3;
        int lane = n_ib*4 + ((kk & 7) >> 1);
        int elem = kk & 1;
        size_t idx = ((((size_t)s*128 + blk)*2 + kpair)*32 + lane)*8 + kodd*4 + reg*2 + elem;
        g_cbfrag[idx] = h;
    }
    g_hn[g] = -0.5f * s2;
}

__global__ void zero_acc() {
    int i = blockIdx.x * 256 + threadIdx.x;
    if (i < SS*KK) g_cnt[i] = 0u;
    if (i < SS)    g_loss[i] = 0.0f;
}

// ---- fused all-stages kernel ----
extern __shared__ char smem_raw[];

#define LOADU(buf, blkbase, p) { \
    _Pragma("unroll") \
    for (int i_ = 0; i_ < 4; i_++) buf[i_] = __ldg(bf4 + (((blkbase) + i_)*2 + (p))*32); }

#define MMAU(base, buf, p) { \
    _Pragma("unroll") \
    for (int i_ = 0; i_ < 4; i_++) { \
        mma16816(acc[(base)+i_], ahf[2*(p)],   buf[i_].x, buf[i_].y); \
        mma16816(acc[(base)+i_], ahf[2*(p)+1], buf[i_].z, buf[i_].w); } }

__global__ __launch_bounds__(256, 2)
void rvq_all(const float* __restrict__ cbs) {
    const int tid  = threadIdx.x;
    const int w    = tid >> 5;
    const int lane = tid & 31;
    const int lq   = lane & 3;
    const int wrow = w >> 1;          // 0..3: rows wrow*16..+15
    const int wcol = w & 1;           // 0..1: blocks wcol*64..+63
    const int row0 = blockIdx.x * TM;
    uint32_t sb;
    asm("{ .reg .u64 t; cvta.to.shared.u64 t, %1; cvt.u32.u64 %0, t; }" : "=r"(sb) : "l"(smem_raw));

    float* hn_all = (float*)(smem_raw + SM_HN);
    float* red    = (float*)(smem_raw + SM_RED);
    float* top4   = (float*)(smem_raw + SM_TOP4);
    float* m4v    = (float*)(smem_raw + SM_M4V);
    float* Af     = (float*)(smem_raw + SM_AF);

    // ---- prologue: fp32 residual tile + ALL stages' (negated) halfnorms ----
    {
        const char* af = (const char*)(g_res + (size_t)row0*DD);
        #pragma unroll
        for (int g = 0; g < 4; g++) {
            int idx = g*256 + tid;              // 1024 granules
            int r = idx >> 4, c = idx & 15;
            cpa16(sb + SM_AF + r*(RSTRF*4) + c*16, af + r*256 + c*16);
        }
        #pragma unroll
        for (int g = 0; g < 8; g++) {
            int idx = g*256 + tid;              // 2048 granules
            cpa16(sb + SM_HN + idx*16, (const char*)g_hn + idx*16);
        }
        cpa_commit();
        cpa_wait0();
    }
    __syncthreads();

    const uint32_t a_addr = sb + SM_AH + (wrow*16 + (lane & 15))*RSTR + (lane >> 4)*16;
    const int r0   = wrow*16 + (lane >> 2);   // thread's first row
    const int slot = wcol*4 + lq;

    for (int stage = 0; stage < SS; stage++) {
        const float* hns = hn_all + stage*KK;
        const float* cb  = cbs + (size_t)stage*KK*DD;

        // build Ah (fp16) from Af — reads only this thread's own quarter-row
        {
            int r  = tid >> 2;
            int k0 = lq * 16;
            const float* src = Af + r*RSTRF + k0;
            __half2* dst = (__half2*)(smem_raw + SM_AH + r*RSTR + k0*2);
            #pragma unroll
            for (int j = 0; j < 8; j++)
                dst[j] = __floats2half2_rn(src[j*2], src[j*2+1]);
        }
        __syncthreads();   // (1) Ah visible to all

        uint32_t ahf[4][4];
        #pragma unroll
        for (int s = 0; s < 4; s++) ldsm_x4(ahf[s], a_addr + s*32);

        const uint4* bf4 = ((const uint4*)g_cbfrag) + (size_t)stage*8192 + lane;

        float v00 = -FLT_MAX, v10 = -FLT_MAX;   // row0 packed top-2
        float v01 = -FLT_MAX, v11 = -FLT_MAX;   // row1 packed top-2

        uint4 bufA[4], bufB[4];
        LOADU(bufA, wcol*64, 0);
        for (int cg = 0; cg < 8; cg++) {
            const int blk0  = wcol*64 + cg*8;
            const int cbase = blk0*8 + lq*2;

            // init accumulators with NEGATED halfnorms (float2 loads)
            float acc[8][4];
            #pragma unroll
            for (int nb = 0; nb < 8; nb++) {
                float2 h2 = *(const float2*)(hns + cbase + nb*8);
                acc[nb][0] = h2.x; acc[nb][1] = h2.y;
                acc[nb][2] = h2.x; acc[nb][3] = h2.y;
            }

            LOADU(bufB, blk0 + 4, 0);
            MMAU(0, bufA, 0);
            LOADU(bufA, blk0, 1);
            MMAU(4, bufB, 0);
            LOADU(bufB, blk0 + 4, 1);
            MMAU(0, bufA, 1);
            if (cg < 7) LOADU(bufA, blk0 + 8, 0);
            MMAU(4, bufB, 1);

            // branchless selection: pair cols, pack pair-id, stream top-2
            const int pidb = blk0*4 + lq;
            #pragma unroll
            for (int nb = 0; nb < 8; nb++) {
                float p0 = fmaxf(acc[nb][0], acc[nb][1]);
                float p1 = fmaxf(acc[nb][2], acc[nb][3]);
                p0 = packf(p0, pidb + nb*4);
                p1 = packf(p1, pidb + nb*4);
                float t0 = fminf(v00, p0); v00 = fmaxf(v00, p0); v10 = fmaxf(v10, t0);
                float t1 = fminf(v01, p1); v01 = fmaxf(v01, p1); v11 = fmaxf(v11, t1);
            }
        }

        // ---- write per-thread packed top-2 (16 entries per row) ----
        m4v[r0*16 + slot*2 + 0]     = v00;
        m4v[r0*16 + slot*2 + 1]     = v10;
        m4v[(r0+8)*16 + slot*2 + 0] = v01;
        m4v[(r0+8)*16 + slot*2 + 1] = v11;
        __syncthreads();   // (2)

        // ---- merge: one thread per row, branchless streaming top-4 of 16 ----
        if (tid < TM) {
            float m0 = -FLT_MAX, m1 = -FLT_MAX, m2 = -FLT_MAX, m3 = -FLT_MAX;
            #pragma unroll
            for (int e = 0; e < 16; e++) {
                float x = m4v[tid*16 + e];
                float t0 = fminf(m0, x); m0 = fmaxf(m0, x);
                float t1 = fminf(m1, t0); m1 = fmaxf(m1, t0);
                float t2 = fminf(m2, t1); m2 = fmaxf(m2, t1);
                m3 = fmaxf(m3, t2);
            }
            top4[tid*4 + 0] = m0;
            top4[tid*4 + 1] = m1;
            top4[tid*4 + 2] = m2;
            top4[tid*4 + 3] = m3;
        }
        __syncthreads();   // (3)

        // ---- exact fp32 rescore: coalesced, lane-cooperative ----
        // 4 lanes of a row each cover their d-quarter of all 8 candidate codes;
        // butterfly shfl gives every lane the full (bit-identical) scores.
        int idx;
        {
            const int row = tid >> 2;
            const float* afq = Af + row*RSTRF + lq*16;
            float a[16];
            #pragma unroll
            for (int j = 0; j < 16; j++) a[j] = afq[j];

            float s[8];
            int   cid[8];
            #pragma unroll
            for (int p = 0; p < 4; p++) {
                uint32_t pid = __float_as_uint(top4[row*4 + p]) & 0x1FFu;
                int c0 = (int)pid * 2;
                cid[p*2]   = c0;
                cid[p*2+1] = c0 + 1;
                const float4* cp0 = (const float4*)(cb + (size_t)c0*DD + lq*16);
                const float4* cp1 = (const float4*)(cb + (size_t)(c0+1)*DD + lq*16);
                float t0 = 0.f, t1 = 0.f;
                #pragma unroll
                for (int u = 0; u < 4; u++) {
                    float4 q0 = __ldg(cp0 + u);
                    float4 q1 = __ldg(cp1 + u);
                    t0 += q0.x*a[u*4] + q0.y*a[u*4+1] + q0.z*a[u*4+2] + q0.w*a[u*4+3];
                    t1 += q1.x*a[u*4] + q1.y*a[u*4+1] + q1.z*a[u*4+2] + q1.w*a[u*4+3];
                }
                s[p*2]   = t0;
                s[p*2+1] = t1;
            }
            #pragma unroll
            for (int e = 0; e < 8; e++) {
                s[e] += __shfl_xor_sync(0xffffffffu, s[e], 1);
                s[e] += __shfl_xor_sync(0xffffffffu, s[e], 2);
                s[e] += hns[cid[e]];
            }
            float best = s[0]; idx = cid[0];
            #pragma unroll
            for (int e = 1; e < 8; e++) {
                if (s[e] > best || (s[e] == best && cid[e] < idx)) { best = s[e]; idx = cid[e]; }
            }
            if (lq == 0) atomicAdd(&g_cnt[stage*KK + idx], 1u);
        }

        // ---- update residual in smem (own quarter); loss partial ----
        {
            const int row = tid >> 2;
            const float4* qv = (const float4*)(cb + (size_t)idx*DD + lq*16);
            float* af = Af + row*RSTRF + lq*16;
            float lsum = 0.0f;
            #pragma unroll
            for (int u = 0; u < 4; u++) {
                float4 q4 = __ldg(qv + u);
                float e0 = q4.x - af[u*4+0];
                float e1 = q4.y - af[u*4+1];
                float e2 = q4.z - af[u*4+2];
                float e3 = q4.w - af[u*4+3];
                lsum += e0*e0 + e1*e1 + e2*e2 + e3*e3;
                af[u*4+0] = -e0; af[u*4+1] = -e1; af[u*4+2] = -e2; af[u*4+3] = -e3;
            }
            #pragma unroll
            for (int o = 16; o > 0; o >>= 1) lsum += __shfl_down_sync(0xffffffffu, lsum, o);
            if (lane == 0) red[stage*8 + w] = lsum;
        }
        // no block sync needed: next stage's Ah build reads only this thread's own Af quarter
    }

    __syncthreads();
    // deferred loss accumulation: one thread per stage
    if (tid < SS) {
        float tot = 0.0f;
        #pragma unroll
        for (int ww = 0; ww < 8; ww++) tot += red[tid*8 + ww];
        atomicAdd(&g_loss[tid], tot);
    }

    // ---- final: q_total = initial residual - final residual ----
    {
        const int row = tid >> 2;
        const float4* rip = (const float4*)(g_res + (size_t)(row0+row)*DD + lq*16);
        float4*       qp  = (float4*)(g_q   + (size_t)(row0+row)*DD + lq*16);
        const float*  af  = Af + row*RSTRF + lq*16;
        #pragma unroll
        for (int u = 0; u < 4; u++) {
            float4 ri = __ldg(rip + u);
            float4 q;
            q.x = ri.x - af[u*4+0];
            q.y = ri.y - af[u*4+1];
            q.z = ri.z - af[u*4+2];
            q.w = ri.w - af[u*4+3];
            qp[u] = q;
        }
    }
}

// ---- losses + perplexities ----
__global__ void finalize(float* __restrict__ out) {
    const int s = blockIdx.x;
    __shared__ float sh[256];
    float e = 0.0f;
    for (int k = threadIdx.x; k < KK; k += 256) {
        float p = (float)g_cnt[s*KK + k] / (float)NV;
        e += p * logf(p + 1e-10f);
    }
    sh[threadIdx.x] = e;
    __syncthreads();
    for (int o = 128; o > 0; o >>= 1) {
        if (threadIdx.x < o) sh[threadIdx.x] += sh[threadIdx.x + o];
        __syncthreads();
    }
    if (threadIdx.x == 0) {
        out[ZQ_ELEMS + s]      = g_loss[s] / (float)(NV*DD);
        out[ZQ_ELEMS + SS + s] = expf(-sh[0]);
    }
}

extern "C" void kernel_launch(void* const* d_in, const int* in_sizes, int n_in,
                              void* d_out, int out_size) {
    const float* z   = (const float*)d_in[0];
    const float* cbs = (const float*)d_in[1];
    float* out = (float*)d_out;

    static int inited = 0;
    if (!inited) {
        cudaFuncSetAttribute(rvq_all, cudaFuncAttributeMaxDynamicSharedMemorySize, SM_TOTAL);
        inited = 1;
    }

    dim3 tb(32, 8);
    transpose_in<<<dim3(TT/32, DD/32, NB), tb>>>(z);
    zero_acc<<<32, 256>>>();
    cb_split<<<(SS*KK)/128, 128>>>(cbs);
    rvq_all<<<NV/TM, 256, SM_TOTAL>>>(cbs);
    finalize<<<SS, 256>>>(out);
    transpose_out<<<dim3(TT/32, DD/32, NB), tb>>>(out);
}

// round 15
// speedup vs baseline: 2.0352x; 1.0293x over previous
#include <cuda_runtime.h>
#include <cuda_fp16.h>
#include <float.h>
#include <cstdint>

#define NB   16
#define TT   4096
#define DD   64
#define KK   1024
#define SS   8
#define NV   (NB*TT)
#define TM   128
#define ZQ_ELEMS (NB*DD*TT)

// ---- device scratch ----
__device__ float        g_res[NV*DD];     // initial residual
__device__ float        g_q[NV*DD];
// fragment-packed codebook (hi, uint4-kpair): [stage][blk(128)][kpair(2)][lane(32)][8 halves]
__device__ __half       g_cbfrag[SS*128*2*32*8];
__device__ float        g_hn[SS*KK];      // NEGATED halfnorms: -0.5*||c||^2
__device__ float        g_loss[SS];
__device__ unsigned int g_cnt[SS*KK];

// ---- smem layout (bytes) ----
#define RSTR     144            // Ah row stride bytes (72 fp16)
#define RSTRF    68             // Af row stride floats (272B)
#define SM_HN    0              // 2 rotating stage buffers: 2*4096 = 8192
#define SM_RED   8192           // 8 stages * 8 warps * 4 = 256
#define SM_TOP4  8448           // 128*4*4 = 2048
#define SM_M4V   10496          // 128*16*4 = 8192
#define SM_AF    18688          // 128*272 = 34816
#define SM_AH    53504          // 128*144 = 18432
#define SM_TOTAL 71936

// ---- PTX helpers ----
__device__ __forceinline__ void cpa16(uint32_t daddr, const void* src) {
    asm volatile("cp.async.cg.shared.global [%0], [%1], 16;" :: "r"(daddr), "l"(src) : "memory");
}
__device__ __forceinline__ void cpa_commit() { asm volatile("cp.async.commit_group;" ::: "memory"); }
__device__ __forceinline__ void cpa_wait0()  { asm volatile("cp.async.wait_group 0;" ::: "memory"); }

__device__ __forceinline__ void ldsm_x4(uint32_t* r, uint32_t a) {
    asm volatile("ldmatrix.sync.aligned.m8n8.x4.shared.b16 {%0,%1,%2,%3}, [%4];"
        : "=r"(r[0]), "=r"(r[1]), "=r"(r[2]), "=r"(r[3]) : "r"(a));
}
__device__ __forceinline__ void mma16816(float* c, const uint32_t* a, uint32_t b0, uint32_t b1) {
    asm volatile("mma.sync.aligned.m16n8k16.row.col.f32.f16.f16.f32 "
        "{%0,%1,%2,%3}, {%4,%5,%6,%7}, {%8,%9}, {%0,%1,%2,%3};"
        : "+f"(c[0]), "+f"(c[1]), "+f"(c[2]), "+f"(c[3])
        : "r"(a[0]), "r"(a[1]), "r"(a[2]), "r"(a[3]), "r"(b0), "r"(b1));
}

// pack 9-bit pair-id into low mantissa bits (perturbation <= 2^-14 relative)
__device__ __forceinline__ float packf(float v, int pid) {
    return __uint_as_float((__float_as_uint(v) & 0xFFFFFE00u) | (unsigned)pid);
}
__device__ __forceinline__ void stream2(float p, float& v0, float& v1) {
    float t = fminf(v0, p); v0 = fmaxf(v0, p); v1 = fmaxf(v1, t);
}

// ---- transpose z [B,D,T] -> g_res [(b,t),d] ----
__global__ void transpose_in(const float* __restrict__ z) {
    __shared__ float tile[32][33];
    const int b  = blockIdx.z;
    const int t0 = blockIdx.x * 32;
    const int d0 = blockIdx.y * 32;
    #pragma unroll
    for (int j = 0; j < 32; j += 8)
        tile[threadIdx.y + j][threadIdx.x] = z[(b*DD + d0 + threadIdx.y + j)*TT + t0 + threadIdx.x];
    __syncthreads();
    #pragma unroll
    for (int j = 0; j < 32; j += 8) {
        int t = t0 + threadIdx.y + j;
        int d = d0 + threadIdx.x;
        g_res[(b*TT + t)*DD + d] = tile[threadIdx.x][threadIdx.y + j];
    }
}

__global__ void transpose_out(float* __restrict__ out) {
    __shared__ float tile[32][33];
    const int b  = blockIdx.z;
    const int t0 = blockIdx.x * 32;
    const int d0 = blockIdx.y * 32;
    #pragma unroll
    for (int j = 0; j < 32; j += 8)
        tile[threadIdx.y + j][threadIdx.x] = g_q[((size_t)b*TT + t0 + threadIdx.y + j)*DD + d0 + threadIdx.x];
    __syncthreads();
    #pragma unroll
    for (int j = 0; j < 32; j += 8)
        out[((size_t)b*DD + d0 + threadIdx.y + j)*TT + t0 + threadIdx.x] = tile[threadIdx.x][threadIdx.y + j];
}

// ---- codebook -> fragment-packed uint4 layout + NEGATED halfnorms ----
__global__ void cb_split(const float* __restrict__ cbs) {
    int g = blockIdx.x * 128 + threadIdx.x;   // 0..8191 = s*1024 + j
    int s    = g >> 10;
    int j    = g & 1023;
    int blk  = j >> 3;
    int n_ib = j & 7;
    const float* src = cbs + (size_t)g * DD;
    float s2 = 0.0f;
    #pragma unroll
    for (int k = 0; k < DD; k++) {
        float v = src[k];
        s2 += v*v;
        __half h = __float2half_rn(v);
        int kstep = k >> 4, kk = k & 15;
        int kpair = kstep >> 1, kodd = kstep & 1;
        int reg  = kk >> 3;
        int lane = n_ib*4 + ((kk & 7) >> 1);
        int elem = kk & 1;
        size_t idx = ((((size_t)s*128 + blk)*2 + kpair)*32 + lane)*8 + kodd*4 + reg*2 + elem;
        g_cbfrag[idx] = h;
    }
    g_hn[g] = -0.5f * s2;
}

__global__ void zero_acc() {
    int i = blockIdx.x * 256 + threadIdx.x;
    if (i < SS*KK) g_cnt[i] = 0u;
    if (i < SS)    g_loss[i] = 0.0f;
}

// ---- fused all-stages kernel: 32 rows/warp, halved B traffic ----
extern __shared__ char smem_raw[];

__global__ __launch_bounds__(256, 2)
void rvq_all(const float* __restrict__ cbs) {
    const int tid  = threadIdx.x;
    const int w    = tid >> 5;
    const int lane = tid & 31;
    const int lq   = lane & 3;
    const int wrow = w >> 1;          // 0..3: rows wrow*32..+31
    const int wcol = w & 1;           // 0..1: blocks wcol*64..+63
    const int row0 = blockIdx.x * TM;
    uint32_t sb;
    asm("{ .reg .u64 t; cvta.to.shared.u64 t, %1; cvt.u32.u64 %0, t; }" : "=r"(sb) : "l"(smem_raw));

    float* hn_b   = (float*)(smem_raw + SM_HN);
    float* red    = (float*)(smem_raw + SM_RED);
    float* top4   = (float*)(smem_raw + SM_TOP4);
    float* m4v    = (float*)(smem_raw + SM_M4V);
    float* Af     = (float*)(smem_raw + SM_AF);

    // ---- prologue: fp32 residual tile + stage-0 (negated) halfnorms ----
    {
        const char* af = (const char*)(g_res + (size_t)row0*DD);
        #pragma unroll
        for (int g = 0; g < 8; g++) {
            int idx = g*256 + tid;              // 2048 granules
            int r = idx >> 4, c = idx & 15;
            cpa16(sb + SM_AF + r*(RSTRF*4) + c*16, af + r*256 + c*16);
        }
        cpa16(sb + SM_HN + tid*16, (const char*)g_hn + tid*16);
        cpa_commit();
        cpa_wait0();
    }
    __syncthreads();

    const uint32_t a_base = sb + SM_AH + (wrow*32 + (lane & 15))*RSTR + (lane >> 4)*16;
    const int rbase = wrow*32 + (lane >> 2);  // first of the 4 owned rows
    const int slot  = wcol*4 + lq;

    for (int stage = 0; stage < SS; stage++) {
        const float* hns = hn_b + (stage & 1)*KK;
        const float* cb  = cbs + (size_t)stage*KK*DD;

        // build Ah (fp16) from Af — own (row, quarter) pairs only
        #pragma unroll
        for (int rr = 0; rr < 2; rr++) {
            int r = (tid >> 2) + rr*64;
            const float* src = Af + r*RSTRF + lq*16;
            uint32_t h[8];
            #pragma unroll
            for (int j = 0; j < 8; j++) {
                __half2 hh = __floats2half2_rn(src[j*2], src[j*2+1]);
                h[j] = *(uint32_t*)&hh;
            }
            uint4* dst = (uint4*)(smem_raw + SM_AH + r*RSTR + lq*32);
            dst[0] = make_uint4(h[0], h[1], h[2], h[3]);
            dst[1] = make_uint4(h[4], h[5], h[6], h[7]);
        }
        cpa_wait0();       // hn(stage) group complete
        __syncthreads();   // (1) Ah + hn(stage) visible
        if (stage < 7) {   // prefetch next stage's hn into the other buffer
            cpa16(sb + SM_HN + ((stage+1)&1)*4096 + tid*16,
                  (const char*)(g_hn + (stage+1)*KK) + tid*16);
            cpa_commit();
        }

        uint32_t ahf[2][4][4];
        #pragma unroll
        for (int rs = 0; rs < 2; rs++)
            #pragma unroll
            for (int s = 0; s < 4; s++)
                ldsm_x4(ahf[rs][s], a_base + rs*16*RSTR + s*32);

        const uint4* bf4 = ((const uint4*)g_cbfrag) + (size_t)stage*8192 + lane;

        float v0[4], v1[4];
        #pragma unroll
        for (int k = 0; k < 4; k++) { v0[k] = -FLT_MAX; v1[k] = -FLT_MAX; }

        uint4 bufA[4], bufB[4];
        #pragma unroll
        for (int i = 0; i < 4; i++)
            bufA[i] = __ldg(bf4 + ((wcol*64 + i)*2 + 0)*32);

        for (int sc = 0; sc < 16; sc++) {
            const int blk0 = wcol*64 + sc*4;

            // init accumulators with NEGATED halfnorms (shared across rowsets)
            float acc[8][4];
            #pragma unroll
            for (int i = 0; i < 4; i++) {
                float2 h2 = *(const float2*)(hns + blk0*8 + i*8 + lq*2);
                acc[i*2][0] = h2.x; acc[i*2][1] = h2.y; acc[i*2][2] = h2.x; acc[i*2][3] = h2.y;
                acc[i*2+1][0] = h2.x; acc[i*2+1][1] = h2.y; acc[i*2+1][2] = h2.x; acc[i*2+1][3] = h2.y;
            }

            #pragma unroll
            for (int i = 0; i < 4; i++)
                bufB[i] = __ldg(bf4 + ((blk0 + i)*2 + 1)*32);
            // kpair 0 (ksteps 0,1) from bufA
            #pragma unroll
            for (int i = 0; i < 4; i++) {
                mma16816(acc[i*2],   ahf[0][0], bufA[i].x, bufA[i].y);
                mma16816(acc[i*2+1], ahf[1][0], bufA[i].x, bufA[i].y);
                mma16816(acc[i*2],   ahf[0][1], bufA[i].z, bufA[i].w);
                mma16816(acc[i*2+1], ahf[1][1], bufA[i].z, bufA[i].w);
            }
            if (sc < 15) {
                #pragma unroll
                for (int i = 0; i < 4; i++)
                    bufA[i] = __ldg(bf4 + ((blk0 + 4 + i)*2 + 0)*32);
            }
            // kpair 1 (ksteps 2,3) from bufB
            #pragma unroll
            for (int i = 0; i < 4; i++) {
                mma16816(acc[i*2],   ahf[0][2], bufB[i].x, bufB[i].y);
                mma16816(acc[i*2+1], ahf[1][2], bufB[i].x, bufB[i].y);
                mma16816(acc[i*2],   ahf[0][3], bufB[i].z, bufB[i].w);
                mma16816(acc[i*2+1], ahf[1][3], bufB[i].z, bufB[i].w);
            }

            // branchless selection: pair cols, pack pair-id, stream top-2
            #pragma unroll
            for (int i = 0; i < 4; i++) {
                int pid = (blk0 + i)*4 + lq;
                float p00 = packf(fmaxf(acc[i*2][0],   acc[i*2][1]),   pid);
                float p01 = packf(fmaxf(acc[i*2][2],   acc[i*2][3]),   pid);
                float p10 = packf(fmaxf(acc[i*2+1][0], acc[i*2+1][1]), pid);
                float p11 = packf(fmaxf(acc[i*2+1][2], acc[i*2+1][3]), pid);
                stream2(p00, v0[0], v1[0]);
                stream2(p01, v0[1], v1[1]);
                stream2(p10, v0[2], v1[2]);
                stream2(p11, v0[3], v1[3]);
            }
        }

        // ---- write per-thread packed top-2: rows rbase, +8, +16, +24 ----
        #pragma unroll
        for (int k = 0; k < 4; k++) {
            int r = rbase + k*8;
            m4v[r*16 + slot*2 + 0] = v0[k];
            m4v[r*16 + slot*2 + 1] = v1[k];
        }
        __syncthreads();   // (2)

        // ---- merge: one thread per row, branchless streaming top-4 of 16 ----
        if (tid < TM) {
            float m0 = -FLT_MAX, m1 = -FLT_MAX, m2 = -FLT_MAX, m3 = -FLT_MAX;
            #pragma unroll
            for (int e = 0; e < 16; e++) {
                float x = m4v[tid*16 + e];
                float t0 = fminf(m0, x); m0 = fmaxf(m0, x);
                float t1 = fminf(m1, t0); m1 = fmaxf(m1, t0);
                float t2 = fminf(m2, t1); m2 = fmaxf(m2, t1);
                m3 = fmaxf(m3, t2);
            }
            top4[tid*4 + 0] = m0;
            top4[tid*4 + 1] = m1;
            top4[tid*4 + 2] = m2;
            top4[tid*4 + 3] = m3;
        }
        __syncthreads();   // (3)

        // ---- exact fp32 rescore + update, 2 rows per thread-quad ----
        float lsum = 0.0f;
        #pragma unroll
        for (int rr = 0; rr < 2; rr++) {
            const int row = (tid >> 2) + rr*64;
            const float* afq = Af + row*RSTRF + lq*16;
            float a[16];
            #pragma unroll
            for (int j = 0; j < 16; j++) a[j] = afq[j];

            float s[8];
            int   cid[8];
            #pragma unroll
            for (int p = 0; p < 4; p++) {
                uint32_t pid = __float_as_uint(top4[row*4 + p]) & 0x1FFu;
                int c0 = (int)pid * 2;
                cid[p*2]   = c0;
                cid[p*2+1] = c0 + 1;
                const float4* cp0 = (const float4*)(cb + (size_t)c0*DD + lq*16);
                const float4* cp1 = (const float4*)(cb + (size_t)(c0+1)*DD + lq*16);
                float t0 = 0.f, t1 = 0.f;
                #pragma unroll
                for (int u = 0; u < 4; u++) {
                    float4 q0 = __ldg(cp0 + u);
                    float4 q1 = __ldg(cp1 + u);
                    t0 += q0.x*a[u*4] + q0.y*a[u*4+1] + q0.z*a[u*4+2] + q0.w*a[u*4+3];
                    t1 += q1.x*a[u*4] + q1.y*a[u*4+1] + q1.z*a[u*4+2] + q1.w*a[u*4+3];
                }
                s[p*2]   = t0;
                s[p*2+1] = t1;
            }
            #pragma unroll
            for (int e = 0; e < 8; e++) {
                s[e] += __shfl_xor_sync(0xffffffffu, s[e], 1);
                s[e] += __shfl_xor_sync(0xffffffffu, s[e], 2);
                s[e] += hns[cid[e]];
            }
            float best = s[0]; int idx = cid[0];
            #pragma unroll
            for (int e = 1; e < 8; e++) {
                if (s[e] > best || (s[e] == best && cid[e] < idx)) { best = s[e]; idx = cid[e]; }
            }
            if (lq == 0) atomicAdd(&g_cnt[stage*KK + idx], 1u);

            // update residual (own quarter)
            const float4* qv = (const float4*)(cb + (size_t)idx*DD + lq*16);
            float* af = Af + row*RSTRF + lq*16;
            #pragma unroll
            for (int u = 0; u < 4; u++) {
                float4 q4 = __ldg(qv + u);
                float e0 = q4.x - a[u*4+0];
                float e1 = q4.y - a[u*4+1];
                float e2 = q4.z - a[u*4+2];
                float e3 = q4.w - a[u*4+3];
                lsum += e0*e0 + e1*e1 + e2*e2 + e3*e3;
                af[u*4+0] = -e0; af[u*4+1] = -e1; af[u*4+2] = -e2; af[u*4+3] = -e3;
            }
        }
        #pragma unroll
        for (int o = 16; o > 0; o >>= 1) lsum += __shfl_down_sync(0xffffffffu, lsum, o);
        if (lane == 0) red[stage*8 + w] = lsum;
        // no block sync: next stage's Ah build reads only this thread's own Af quarters
    }

    __syncthreads();
    if (tid < SS) {
        float tot = 0.0f;
        #pragma unroll
        for (int ww = 0; ww < 8; ww++) tot += red[tid*8 + ww];
        atomicAdd(&g_loss[tid], tot);
    }

    // ---- final: q_total = initial residual - final residual ----
    #pragma unroll
    for (int rr = 0; rr < 2; rr++) {
        const int row = (tid >> 2) + rr*64;
        const float4* rip = (const float4*)(g_res + (size_t)(row0+row)*DD + lq*16);
        float4*       qp  = (float4*)(g_q   + (size_t)(row0+row)*DD + lq*16);
        const float*  af  = Af + row*RSTRF + lq*16;
        #pragma unroll
        for (int u = 0; u < 4; u++) {
            float4 ri = __ldg(rip + u);
            float4 q;
            q.x = ri.x - af[u*4+0];
            q.y = ri.y - af[u*4+1];
            q.z = ri.z - af[u*4+2];
            q.w = ri.w - af[u*4+3];
            qp[u] = q;
        }
    }
}

// ---- losses + perplexities ----
__global__ void finalize(float* __restrict__ out) {
    const int s = blockIdx.x;
    __shared__ float sh[256];
    float e = 0.0f;
    for (int k = threadIdx.x; k < KK; k += 256) {
        float p = (float)g_cnt[s*KK + k] / (float)NV;
        e += p * logf(p + 1e-10f);
    }
    sh[threadIdx.x] = e;
    __syncthreads();
    for (int o = 128; o > 0; o >>= 1) {
        if (threadIdx.x < o) sh[threadIdx.x] += sh[threadIdx.x + o];
        __syncthreads();
    }
    if (threadIdx.x == 0) {
        out[ZQ_ELEMS + s]      = g_loss[s] / (float)(NV*DD);
        out[ZQ_ELEMS + SS + s] = expf(-sh[0]);
    }
}

extern "C" void kernel_launch(void* const* d_in, const int* in_sizes, int n_in,
                              void* d_out, int out_size) {
    const float* z   = (const float*)d_in[0];
    const float* cbs = (const float*)d_in[1];
    float* out = (float*)d_out;

    static int inited = 0;
    if (!inited) {
        cudaFuncSetAttribute(rvq_all, cudaFuncAttributeMaxDynamicSharedMemorySize, SM_TOTAL);
        inited = 1;
    }

    dim3 tb(32, 8);
    transpose_in<<<dim3(TT/32, DD/32, NB), tb>>>(z);
    zero_acc<<<32, 256>>>();
    cb_split<<<(SS*KK)/128, 128>>>(cbs);
    rvq_all<<<NV/TM, 256, SM_TOTAL>>>(cbs);
    finalize<<<SS, 256>>>(out);
    transpose_out<<<dim3(TT/32, DD/32, NB), tb>>>(out);
}

// round 16
// speedup vs baseline: 2.0371x; 1.0009x over previous
#include <cuda_runtime.h>
#include <cuda_fp16.h>
#include <float.h>
#include <cstdint>

#define NB   16
#define TT   4096
#define DD   64
#define KK   1024
#define SS   8
#define NV   (NB*TT)
#define TM   128
#define ZQ_ELEMS (NB*DD*TT)

// ---- device scratch ----
__device__ float        g_res[NV*DD];     // initial residual
__device__ float        g_q[NV*DD];
// fragment-packed codebook (hi, uint4-kpair): [stage][blk(128)][kpair(2)][lane(32)][8 halves]
__device__ __half       g_cbfrag[SS*128*2*32*8];
__device__ float        g_hn[SS*KK];      // NEGATED halfnorms: -0.5*||c||^2
__device__ float        g_loss[SS];
__device__ unsigned int g_cnt[SS*KK];

// ---- smem layout (bytes) ----
#define RSTR     144            // Ah row stride bytes (72 fp16)
#define RSTRF    68             // Af row stride floats (272B)
#define SM_HN    0              // 2 rotating stage buffers: 2*4096 = 8192
#define SM_RED   8192           // 8 stages * 8 warps * 4 = 256
#define SM_TOP4  8448           // 128*4*4 = 2048
#define SM_M4V   10496          // 128*16*4 = 8192
#define SM_AF    18688          // 128*272 = 34816
#define SM_AH    53504          // 128*144 = 18432
#define SM_TOTAL 71936

// ---- PTX helpers ----
__device__ __forceinline__ void cpa16(uint32_t daddr, const void* src) {
    asm volatile("cp.async.cg.shared.global [%0], [%1], 16;" :: "r"(daddr), "l"(src) : "memory");
}
__device__ __forceinline__ void cpa_commit() { asm volatile("cp.async.commit_group;" ::: "memory"); }
__device__ __forceinline__ void cpa_wait0()  { asm volatile("cp.async.wait_group 0;" ::: "memory"); }

__device__ __forceinline__ void ldsm_x4(uint32_t* r, uint32_t a) {
    asm volatile("ldmatrix.sync.aligned.m8n8.x4.shared.b16 {%0,%1,%2,%3}, [%4];"
        : "=r"(r[0]), "=r"(r[1]), "=r"(r[2]), "=r"(r[3]) : "r"(a));
}
__device__ __forceinline__ void mma16816(float* c, const uint32_t* a, uint32_t b0, uint32_t b1) {
    asm volatile("mma.sync.aligned.m16n8k16.row.col.f32.f16.f16.f32 "
        "{%0,%1,%2,%3}, {%4,%5,%6,%7}, {%8,%9}, {%0,%1,%2,%3};"
        : "+f"(c[0]), "+f"(c[1]), "+f"(c[2]), "+f"(c[3])
        : "r"(a[0]), "r"(a[1]), "r"(a[2]), "r"(a[3]), "r"(b0), "r"(b1));
}
// first MMA of a sub-chunk: D = A*B + {h0,h1,h0,h1} — inits accumulators for free
__device__ __forceinline__ void mma16816_init(float* d, const uint32_t* a, uint32_t b0, uint32_t b1,
                                              float h0, float h1) {
    asm volatile("mma.sync.aligned.m16n8k16.row.col.f32.f16.f16.f32 "
        "{%0,%1,%2,%3}, {%4,%5,%6,%7}, {%8,%9}, {%10,%11,%10,%11};"
        : "=f"(d[0]), "=f"(d[1]), "=f"(d[2]), "=f"(d[3])
        : "r"(a[0]), "r"(a[1]), "r"(a[2]), "r"(a[3]), "r"(b0), "r"(b1), "f"(h0), "f"(h1));
}

// pack 9-bit pair-id into low mantissa bits (perturbation <= 2^-14 relative)
__device__ __forceinline__ float packf(float v, int pid) {
    return __uint_as_float((__float_as_uint(v) & 0xFFFFFE00u) | (unsigned)pid);
}
__device__ __forceinline__ void stream2(float p, float& v0, float& v1) {
    float t = fminf(v0, p); v0 = fmaxf(v0, p); v1 = fmaxf(v1, t);
}

// ---- transpose z [B,D,T] -> g_res [(b,t),d] ----
__global__ void transpose_in(const float* __restrict__ z) {
    __shared__ float tile[32][33];
    const int b  = blockIdx.z;
    const int t0 = blockIdx.x * 32;
    const int d0 = blockIdx.y * 32;
    #pragma unroll
    for (int j = 0; j < 32; j += 8)
        tile[threadIdx.y + j][threadIdx.x] = z[(b*DD + d0 + threadIdx.y + j)*TT + t0 + threadIdx.x];
    __syncthreads();
    #pragma unroll
    for (int j = 0; j < 32; j += 8) {
        int t = t0 + threadIdx.y + j;
        int d = d0 + threadIdx.x;
        g_res[(b*TT + t)*DD + d] = tile[threadIdx.x][threadIdx.y + j];
    }
}

__global__ void transpose_out(float* __restrict__ out) {
    __shared__ float tile[32][33];
    const int b  = blockIdx.z;
    const int t0 = blockIdx.x * 32;
    const int d0 = blockIdx.y * 32;
    #pragma unroll
    for (int j = 0; j < 32; j += 8)
        tile[threadIdx.y + j][threadIdx.x] = g_q[((size_t)b*TT + t0 + threadIdx.y + j)*DD + d0 + threadIdx.x];
    __syncthreads();
    #pragma unroll
    for (int j = 0; j < 32; j += 8)
        out[((size_t)b*DD + d0 + threadIdx.y + j)*TT + t0 + threadIdx.x] = tile[threadIdx.x][threadIdx.y + j];
}

// ---- codebook -> fragment-packed uint4 layout + NEGATED halfnorms ----
__global__ void cb_split(const float* __restrict__ cbs) {
    int g = blockIdx.x * 128 + threadIdx.x;   // 0..8191 = s*1024 + j
    int s    = g >> 10;
    int j    = g & 1023;
    int blk  = j >> 3;
    int n_ib = j & 7;
    const float* src = cbs + (size_t)g * DD;
    float s2 = 0.0f;
    #pragma unroll
    for (int k = 0; k < DD; k++) {
        float v = src[k];
        s2 += v*v;
        __half h = __float2half_rn(v);
        int kstep = k >> 4, kk = k & 15;
        int kpair = kstep >> 1, kodd = kstep & 1;
        int reg  = kk >> 3;
        int lane = n_ib*4 + ((kk & 7) >> 1);
        int elem = kk & 1;
        size_t idx = ((((size_t)s*128 + blk)*2 + kpair)*32 + lane)*8 + kodd*4 + reg*2 + elem;
        g_cbfrag[idx] = h;
    }
    g_hn[g] = -0.5f * s2;
}

__global__ void zero_acc() {
    int i = blockIdx.x * 256 + threadIdx.x;
    if (i < SS*KK) g_cnt[i] = 0u;
    if (i < SS)    g_loss[i] = 0.0f;
}

// ---- fused all-stages kernel: 32 rows/warp, halved B traffic ----
extern __shared__ char smem_raw[];

__global__ __launch_bounds__(256, 2)
void rvq_all(const float* __restrict__ cbs) {
    const int tid  = threadIdx.x;
    const int w    = tid >> 5;
    const int lane = tid & 31;
    const int lq   = lane & 3;
    const int wrow = w >> 1;          // 0..3: rows wrow*32..+31
    const int wcol = w & 1;           // 0..1: blocks wcol*64..+63
    const int row0 = blockIdx.x * TM;
    uint32_t sb;
    asm("{ .reg .u64 t; cvta.to.shared.u64 t, %1; cvt.u32.u64 %0, t; }" : "=r"(sb) : "l"(smem_raw));

    float* hn_b   = (float*)(smem_raw + SM_HN);
    float* red    = (float*)(smem_raw + SM_RED);
    float* top4   = (float*)(smem_raw + SM_TOP4);
    float* m4v    = (float*)(smem_raw + SM_M4V);
    float* Af     = (float*)(smem_raw + SM_AF);

    // ---- prologue: fp32 residual tile + stage-0 (negated) halfnorms ----
    {
        const char* af = (const char*)(g_res + (size_t)row0*DD);
        #pragma unroll
        for (int g = 0; g < 8; g++) {
            int idx = g*256 + tid;              // 2048 granules
            int r = idx >> 4, c = idx & 15;
            cpa16(sb + SM_AF + r*(RSTRF*4) + c*16, af + r*256 + c*16);
        }
        cpa16(sb + SM_HN + tid*16, (const char*)g_hn + tid*16);
        cpa_commit();
        cpa_wait0();
    }
    __syncthreads();

    const uint32_t a_base = sb + SM_AH + (wrow*32 + (lane & 15))*RSTR + (lane >> 4)*16;
    const int rbase = wrow*32 + (lane >> 2);  // first of the 4 owned rows
    const int slot  = wcol*4 + lq;

    for (int stage = 0; stage < SS; stage++) {
        const float* hns = hn_b + (stage & 1)*KK;
        const float* cb  = cbs + (size_t)stage*KK*DD;

        // build Ah (fp16) from Af — own (row, quarter) pairs only
        #pragma unroll
        for (int rr = 0; rr < 2; rr++) {
            int r = (tid >> 2) + rr*64;
            const float* src = Af + r*RSTRF + lq*16;
            uint32_t h[8];
            #pragma unroll
            for (int j = 0; j < 8; j++) {
                __half2 hh = __floats2half2_rn(src[j*2], src[j*2+1]);
                h[j] = *(uint32_t*)&hh;
            }
            uint4* dst = (uint4*)(smem_raw + SM_AH + r*RSTR + lq*32);
            dst[0] = make_uint4(h[0], h[1], h[2], h[3]);
            dst[1] = make_uint4(h[4], h[5], h[6], h[7]);
        }
        cpa_wait0();       // hn(stage) group complete
        __syncthreads();   // (1) Ah + hn(stage) visible
        if (stage < 7) {   // prefetch next stage's hn into the other buffer
            cpa16(sb + SM_HN + ((stage+1)&1)*4096 + tid*16,
                  (const char*)(g_hn + (stage+1)*KK) + tid*16);
            cpa_commit();
        }

        uint32_t ahf[2][4][4];
        #pragma unroll
        for (int rs = 0; rs < 2; rs++)
            #pragma unroll
            for (int s = 0; s < 4; s++)
                ldsm_x4(ahf[rs][s], a_base + rs*16*RSTR + s*32);

        const uint4* bf4 = ((const uint4*)g_cbfrag) + (size_t)stage*8192 + lane;

        float v0[4], v1[4];
        #pragma unroll
        for (int k = 0; k < 4; k++) { v0[k] = -FLT_MAX; v1[k] = -FLT_MAX; }

        uint4 bufA[4], bufB[4];
        #pragma unroll
        for (int i = 0; i < 4; i++)
            bufA[i] = __ldg(bf4 + ((wcol*64 + i)*2 + 0)*32);

        for (int sc = 0; sc < 16; sc++) {
            const int blk0 = wcol*64 + sc*4;

            // negated halfnorm pairs for this sub-chunk (consumed by init-MMA C operand)
            float2 h2[4];
            #pragma unroll
            for (int i = 0; i < 4; i++)
                h2[i] = *(const float2*)(hns + blk0*8 + i*8 + lq*2);

            float acc[8][4];
            #pragma unroll
            for (int i = 0; i < 4; i++)
                bufB[i] = __ldg(bf4 + ((blk0 + i)*2 + 1)*32);
            // kpair 0 (ksteps 0,1) from bufA; first MMA initializes acc with -hn
            #pragma unroll
            for (int i = 0; i < 4; i++) {
                mma16816_init(acc[i*2],   ahf[0][0], bufA[i].x, bufA[i].y, h2[i].x, h2[i].y);
                mma16816_init(acc[i*2+1], ahf[1][0], bufA[i].x, bufA[i].y, h2[i].x, h2[i].y);
                mma16816(acc[i*2],   ahf[0][1], bufA[i].z, bufA[i].w);
                mma16816(acc[i*2+1], ahf[1][1], bufA[i].z, bufA[i].w);
            }
            if (sc < 15) {
                #pragma unroll
                for (int i = 0; i < 4; i++)
                    bufA[i] = __ldg(bf4 + ((blk0 + 4 + i)*2 + 0)*32);
            }
            // kpair 1 (ksteps 2,3) from bufB
            #pragma unroll
            for (int i = 0; i < 4; i++) {
                mma16816(acc[i*2],   ahf[0][2], bufB[i].x, bufB[i].y);
                mma16816(acc[i*2+1], ahf[1][2], bufB[i].x, bufB[i].y);
                mma16816(acc[i*2],   ahf[0][3], bufB[i].z, bufB[i].w);
                mma16816(acc[i*2+1], ahf[1][3], bufB[i].z, bufB[i].w);
            }

            // branchless selection: pair cols, pack pair-id, stream top-2
            #pragma unroll
            for (int i = 0; i < 4; i++) {
                int pid = (blk0 + i)*4 + lq;
                float p00 = packf(fmaxf(acc[i*2][0],   acc[i*2][1]),   pid);
                float p01 = packf(fmaxf(acc[i*2][2],   acc[i*2][3]),   pid);
                float p10 = packf(fmaxf(acc[i*2+1][0], acc[i*2+1][1]), pid);
                float p11 = packf(fmaxf(acc[i*2+1][2], acc[i*2+1][3]), pid);
                stream2(p00, v0[0], v1[0]);
                stream2(p01, v0[1], v1[1]);
                stream2(p10, v0[2], v1[2]);
                stream2(p11, v0[3], v1[3]);
            }
        }

        // ---- write per-thread packed top-2: rows rbase, +8, +16, +24 ----
        #pragma unroll
        for (int k = 0; k < 4; k++) {
            int r = rbase + k*8;
            m4v[r*16 + slot*2 + 0] = v0[k];
            m4v[r*16 + slot*2 + 1] = v1[k];
        }
        __syncthreads();   // (2)

        // ---- merge: one thread per row, branchless streaming top-4 of 16 ----
        if (tid < TM) {
            float m0 = -FLT_MAX, m1 = -FLT_MAX, m2 = -FLT_MAX, m3 = -FLT_MAX;
            #pragma unroll
            for (int e = 0; e < 16; e++) {
                float x = m4v[tid*16 + e];
                float t0 = fminf(m0, x); m0 = fmaxf(m0, x);
                float t1 = fminf(m1, t0); m1 = fmaxf(m1, t0);
                float t2 = fminf(m2, t1); m2 = fmaxf(m2, t1);
                m3 = fmaxf(m3, t2);
            }
            top4[tid*4 + 0] = m0;
            top4[tid*4 + 1] = m1;
            top4[tid*4 + 2] = m2;
            top4[tid*4 + 3] = m3;
        }
        __syncthreads();   // (3)

        // ---- exact fp32 rescore + update, 2 rows per thread-quad ----
        float lsum = 0.0f;
        #pragma unroll
        for (int rr = 0; rr < 2; rr++) {
            const int row = (tid >> 2) + rr*64;
            const float* afq = Af + row*RSTRF + lq*16;
            float a[16];
            #pragma unroll
            for (int j = 0; j < 16; j++) a[j] = afq[j];

            float s[8];
            int   cid[8];
            #pragma unroll
            for (int p = 0; p < 4; p++) {
                uint32_t pid = __float_as_uint(top4[row*4 + p]) & 0x1FFu;
                int c0 = (int)pid * 2;
                cid[p*2]   = c0;
                cid[p*2+1] = c0 + 1;
                const float4* cp0 = (const float4*)(cb + (size_t)c0*DD + lq*16);
                const float4* cp1 = (const float4*)(cb + (size_t)(c0+1)*DD + lq*16);
                float t0 = 0.f, t1 = 0.f;
                #pragma unroll
                for (int u = 0; u < 4; u++) {
                    float4 q0 = __ldg(cp0 + u);
                    float4 q1 = __ldg(cp1 + u);
                    t0 += q0.x*a[u*4] + q0.y*a[u*4+1] + q0.z*a[u*4+2] + q0.w*a[u*4+3];
                    t1 += q1.x*a[u*4] + q1.y*a[u*4+1] + q1.z*a[u*4+2] + q1.w*a[u*4+3];
                }
                s[p*2]   = t0;
                s[p*2+1] = t1;
            }
            #pragma unroll
            for (int e = 0; e < 8; e++) {
                s[e] += __shfl_xor_sync(0xffffffffu, s[e], 1);
                s[e] += __shfl_xor_sync(0xffffffffu, s[e], 2);
                s[e] += hns[cid[e]];
            }
            float best = s[0]; int idx = cid[0];
            #pragma unroll
            for (int e = 1; e < 8; e++) {
                if (s[e] > best || (s[e] == best && cid[e] < idx)) { best = s[e]; idx = cid[e]; }
            }
            if (lq == 0) atomicAdd(&g_cnt[stage*KK + idx], 1u);

            // update residual (own quarter)
            const float4* qv = (const float4*)(cb + (size_t)idx*DD + lq*16);
            float* af = Af + row*RSTRF + lq*16;
            #pragma unroll
            for (int u = 0; u < 4; u++) {
                float4 q4 = __ldg(qv + u);
                float e0 = q4.x - a[u*4+0];
                float e1 = q4.y - a[u*4+1];
                float e2 = q4.z - a[u*4+2];
                float e3 = q4.w - a[u*4+3];
                lsum += e0*e0 + e1*e1 + e2*e2 + e3*e3;
                af[u*4+0] = -e0; af[u*4+1] = -e1; af[u*4+2] = -e2; af[u*4+3] = -e3;
            }
        }
        #pragma unroll
        for (int o = 16; o > 0; o >>= 1) lsum += __shfl_down_sync(0xffffffffu, lsum, o);
        if (lane == 0) red[stage*8 + w] = lsum;
        // no block sync: next stage's Ah build reads only this thread's own Af quarters
    }

    __syncthreads();
    if (tid < SS) {
        float tot = 0.0f;
        #pragma unroll
        for (int ww = 0; ww < 8; ww++) tot += red[tid*8 + ww];
        atomicAdd(&g_loss[tid], tot);
    }

    // ---- final: q_total = initial residual - final residual ----
    #pragma unroll
    for (int rr = 0; rr < 2; rr++) {
        const int row = (tid >> 2) + rr*64;
        const float4* rip = (const float4*)(g_res + (size_t)(row0+row)*DD + lq*16);
        float4*       qp  = (float4*)(g_q   + (size_t)(row0+row)*DD + lq*16);
        const float*  af  = Af + row*RSTRF + lq*16;
        #pragma unroll
        for (int u = 0; u < 4; u++) {
            float4 ri = __ldg(rip + u);
            float4 q;
            q.x = ri.x - af[u*4+0];
            q.y = ri.y - af[u*4+1];
            q.z = ri.z - af[u*4+2];
            q.w = ri.w - af[u*4+3];
            qp[u] = q;
        }
    }
}

// ---- losses + perplexities ----
__global__ void finalize(float* __restrict__ out) {
    const int s = blockIdx.x;
    __shared__ float sh[256];
    float e = 0.0f;
    for (int k = threadIdx.x; k < KK; k += 256) {
        float p = (float)g_cnt[s*KK + k] / (float)NV;
        e += p * logf(p + 1e-10f);
    }
    sh[threadIdx.x] = e;
    __syncthreads();
    for (int o = 128; o > 0; o >>= 1) {
        if (threadIdx.x < o) sh[threadIdx.x] += sh[threadIdx.x + o];
        __syncthreads();
    }
    if (threadIdx.x == 0) {
        out[ZQ_ELEMS + s]      = g_loss[s] / (float)(NV*DD);
        out[ZQ_ELEMS + SS + s] = expf(-sh[0]);
    }
}

extern "C" void kernel_launch(void* const* d_in, const int* in_sizes, int n_in,
                              void* d_out, int out_size) {
    const float* z   = (const float*)d_in[0];
    const float* cbs = (const float*)d_in[1];
    float* out = (float*)d_out;

    static int inited = 0;
    if (!inited) {
        cudaFuncSetAttribute(rvq_all, cudaFuncAttributeMaxDynamicSharedMemorySize, SM_TOTAL);
        inited = 1;
    }

    dim3 tb(32, 8);
    transpose_in<<<dim3(TT/32, DD/32, NB), tb>>>(z);
    zero_acc<<<32, 256>>>();
    cb_split<<<(SS*KK)/128, 128>>>(cbs);
    rvq_all<<<NV/TM, 256, SM_TOTAL>>>(cbs);
    finalize<<<SS, 256>>>(out);
    transpose_out<<<dim3(TT/32, DD/32, NB), tb>>>(out);
}